// round 11
// baseline (speedup 1.0000x reference)
#include <cuda_runtime.h>
#include <cuda_fp16.h>

// GaussianLayer: 2D Gaussian "same" conv (25x25, center tap zeroed) over
// src (4,512,512,21) NHWC fp32.  dst = g_y * (g_x * src) - src.
// Round 10: pass_v reverted to exact round-6 form (no reg cap, no hints).
// pass_h: identical compute, but block = one row (672 thr); fp16 results
// staged in smem and written back as coalesced uint4 (kills 16x STG.16
// scatter + write amplification).

#define BATCH 4
#define HH    512
#define WW    512
#define CC    21
#define RR    12
#define TAPS  25
#define ROWF  (WW * CC)          /* 10752 floats per (b,y) row */
#define IMGF  (HH * ROWF)
#define TOTALF (BATCH * IMGF)    /* 22,020,096 */

typedef unsigned long long u64;

// 16B-aligned fp16 scratch (uint4 writeback), 44 MB, L2-resident for pass_v
__device__ __align__(16) __half g_tmp[TOTALF];

__device__ __forceinline__ u64 pack2(float lo, float hi) {
    u64 r; asm("mov.b64 %0, {%1, %2};" : "=l"(r) : "f"(lo), "f"(hi)); return r;
}
__device__ __forceinline__ void fma2(u64& d, u64 a, u64 b) {
    asm("fma.rn.f32x2 %0, %1, %2, %0;" : "+l"(d) : "l"(a), "l"(b));
}
__device__ __forceinline__ float2 unpack2(u64 v) {
    float2 f; asm("mov.b64 {%0, %1}, %2;" : "=f"(f.x), "=f"(f.y) : "l"(v)); return f;
}

// 13 symmetric 1D weights from row RR of the 2D kernel; center weight = 1
// (the zeroed 2D center tap is handled by subtracting src at the end).
__device__ __forceinline__ void load_weights(const float* __restrict__ k, u64* W2) {
#pragma unroll
    for (int j = 0; j < 12; ++j) {
        float w = __ldg(k + RR * TAPS + j);
        W2[j] = pack2(w, w);
    }
    W2[12] = pack2(1.0f, 1.0f);
}

// ---------------- Pass 1: horizontal. Block = one (b,y) row, 672 threads. ---
// Thread = (channel c, 16 adjacent x outputs); window of 40 front-batched
// L1-served loads; FFMA2 pairs (identical compute to round 6).  Results
// staged in smem, then written back as 1344 coalesced uint4 stores.
__global__ void __launch_bounds__(672) pass_h_kernel(const float* __restrict__ src,
                                                     const float* __restrict__ k) {
    __shared__ __align__(16) __half s_out[ROWF];    // 21504 B

    const int row = blockIdx.x;                     // b*HH + y
    const int rem = threadIdx.x;                    // 0..671
    int xg = rem / CC;                              // 0..31
    int c  = rem - xg * CC;                         // 0..20
    int x0 = xg * 16;

    const float* rp = src + (size_t)row * ROWF;
    int base = x0 * CC + c;

    u64 W2[13];
    load_weights(k, W2);

    float v[40];
    if (x0 >= RR && x0 + 27 < WW) {                 // interior
#pragma unroll
        for (int s = 0; s < 40; ++s)
            v[s] = rp[base + (s - RR) * CC];
    } else {
#pragma unroll
        for (int s = 0; s < 40; ++s) {
            int xin = x0 - RR + s;
            v[s] = (xin >= 0 && xin < WW) ? rp[base + (s - RR) * CC] : 0.0f;
        }
    }

    // A[m] accumulates outputs (x0+2m, x0+2m+1), m = 0..7
    u64 A[8] = {0ull, 0ull, 0ull, 0ull, 0ull, 0ull, 0ull, 0ull};
#pragma unroll
    for (int i = 0; i < 39; ++i) {
        u64 P = pack2(v[i], v[i + 1]);
#pragma unroll
        for (int m = 0; m < 8; ++m) {
            int n = i - 2 * m;
            if (n >= 0 && n < TAPS)
                fma2(A[m], W2[n <= RR ? n : 24 - n], P);
        }
    }

#pragma unroll
    for (int m = 0; m < 8; ++m) {
        float2 o = unpack2(A[m]);
        s_out[base + (2 * m)     * CC] = __float2half_rn(o.x);
        s_out[base + (2 * m + 1) * CC] = __float2half_rn(o.y);
    }
    __syncthreads();

    // Coalesced writeback: 1344 uint4 per row, 2 per thread.
    uint4* op = (uint4*)(g_tmp + (size_t)row * ROWF);
    const uint4* os = (const uint4*)s_out;
#pragma unroll
    for (int i = 0; i < 2; ++i)
        op[rem + i * 672] = os[rem + i * 672];
}

// ---------------- Pass 2: vertical + subtract src (exact round-6 form) -----
__global__ void __launch_bounds__(256) pass_v_kernel(const float* __restrict__ src,
                                                     const float* __restrict__ k,
                                                     float* __restrict__ dst) {
    const int PAIRS = ROWF / 2;                     // 5376 pairs per row
    const int PER_B = (HH / 8) * PAIRS;             // 344,064 threads per batch
    int tid = blockIdx.x * 256 + threadIdx.x;

    int b   = tid / PER_B;
    int rem = tid - b * PER_B;
    int yg  = rem / PAIRS;
    int fp  = rem - yg * PAIRS;
    int y0  = yg * 8;

    size_t off = (size_t)b * IMGF + 2 * (size_t)fp;
    const __half* tp = g_tmp + off;
    const float*  sp = src + off;
    float*        dp = dst + off;

    u64 W2[13];
    load_weights(k, W2);

    __half2 v[32];
    if (y0 >= RR && y0 + 19 < HH) {
#pragma unroll
        for (int s = 0; s < 32; ++s)
            v[s] = *(const __half2*)(tp + (size_t)(y0 - RR + s) * ROWF);
    } else {
        const __half2 z = __float2half2_rn(0.0f);
#pragma unroll
        for (int s = 0; s < 32; ++s) {
            int yin = y0 - RR + s;
            v[s] = (yin >= 0 && yin < HH)
                       ? *(const __half2*)(tp + (size_t)yin * ROWF)
                       : z;
        }
    }

    u64 A[8] = {0ull, 0ull, 0ull, 0ull, 0ull, 0ull, 0ull, 0ull};
#pragma unroll
    for (int s = 0; s < 32; ++s) {
        float2 f = __half22float2(v[s]);
        u64 P = pack2(f.x, f.y);
#pragma unroll
        for (int m = 0; m < 8; ++m) {
            int n = s - m;
            if (n >= 0 && n < TAPS)
                fma2(A[m], W2[n <= RR ? n : 24 - n], P);
        }
    }

#pragma unroll
    for (int m = 0; m < 8; ++m) {
        float2 o  = unpack2(A[m]);
        float2 s2 = *(const float2*)(sp + (size_t)(y0 + m) * ROWF);
        float2 r;
        r.x = o.x - s2.x;
        r.y = o.y - s2.y;
        *(float2*)(dp + (size_t)(y0 + m) * ROWF) = r;
    }
}

extern "C" void kernel_launch(void* const* d_in, const int* in_sizes, int n_in,
                              void* d_out, int out_size) {
    const float* src = (const float*)d_in[0];
    const float* k   = (const float*)d_in[1];
    float*       dst = (float*)d_out;

    pass_h_kernel<<<BATCH * HH, 672>>>(src, k);           // 1 block per row

    int nthreads_v = BATCH * (HH / 8) * (ROWF / 2);       // 1,376,256
    pass_v_kernel<<<nthreads_v / 256, 256>>>(src, k, dst);
}

// round 12
// speedup vs baseline: 1.3382x; 1.3382x over previous
#include <cuda_runtime.h>
#include <cuda_fp16.h>

// GaussianLayer: 2D Gaussian "same" conv (25x25, center tap zeroed) over
// src (4,512,512,21) NHWC fp32.  dst = g_y * (g_x * src) - src.
// Round 12: round-6 champion + one bounded pass_v change: src loads issued
// FIRST and folded into the accumulator init (A[m] = -src), removing the
// exposed DRAM latency + 16 FADDs from the warp tail.  Zero reg delta.

#define BATCH 4
#define HH    512
#define WW    512
#define CC    21
#define RR    12
#define TAPS  25
#define ROWF  (WW * CC)          /* 10752 floats per (b,y) row */
#define IMGF  (HH * ROWF)
#define TOTALF (BATCH * IMGF)    /* 22,020,096 */

typedef unsigned long long u64;

__device__ __half g_tmp[TOTALF];   // 44 MB fp16 scratch (L2-resident for pass_v)

__device__ __forceinline__ u64 pack2(float lo, float hi) {
    u64 r; asm("mov.b64 %0, {%1, %2};" : "=l"(r) : "f"(lo), "f"(hi)); return r;
}
__device__ __forceinline__ void fma2(u64& d, u64 a, u64 b) {
    asm("fma.rn.f32x2 %0, %1, %2, %0;" : "+l"(d) : "l"(a), "l"(b));
}
__device__ __forceinline__ float2 unpack2(u64 v) {
    float2 f; asm("mov.b64 {%0, %1}, %2;" : "=f"(f.x), "=f"(f.y) : "l"(v)); return f;
}

// 13 symmetric 1D weights from row RR of the 2D kernel; center weight = 1
// (the zeroed 2D center tap is handled by subtracting src at the end).
__device__ __forceinline__ void load_weights(const float* __restrict__ k, u64* W2) {
#pragma unroll
    for (int j = 0; j < 12; ++j) {
        float w = __ldg(k + RR * TAPS + j);
        W2[j] = pack2(w, w);
    }
    W2[12] = pack2(1.0f, 1.0f);
}

// ---------------- Pass 1: horizontal. 16 adjacent x outputs per thread, -----
// scalar sliding window of 40 front-batched loads (L1-served), FFMA2 pairs.
// (exact round-6 form — best measured)
__global__ void __launch_bounds__(256) pass_h_kernel(const float* __restrict__ src,
                                                     const float* __restrict__ k) {
    const int PER_ROW = (WW / 16) * CC;             // 672 threads per (b,y) row
    int tid = blockIdx.x * 256 + threadIdx.x;       // grid sized exactly

    int row = tid / PER_ROW;                        // b*HH + y
    int rem = tid - row * PER_ROW;
    int xg  = rem / CC;
    int c   = rem - xg * CC;
    int x0  = xg * 16;

    const float* rp = src   + (size_t)row * ROWF;
    __half*      op = g_tmp + (size_t)row * ROWF;
    int base = x0 * CC + c;

    u64 W2[13];
    load_weights(k, W2);

    float v[40];
    if (x0 >= RR && x0 + 27 < WW) {                 // interior: xin in range
#pragma unroll
        for (int s = 0; s < 40; ++s)
            v[s] = rp[base + (s - RR) * CC];
    } else {
#pragma unroll
        for (int s = 0; s < 40; ++s) {
            int xin = x0 - RR + s;
            v[s] = (xin >= 0 && xin < WW) ? rp[base + (s - RR) * CC] : 0.0f;
        }
    }

    // A[m] accumulates outputs (x0+2m, x0+2m+1), m = 0..7
    u64 A[8] = {0ull, 0ull, 0ull, 0ull, 0ull, 0ull, 0ull, 0ull};
#pragma unroll
    for (int i = 0; i < 39; ++i) {
        u64 P = pack2(v[i], v[i + 1]);
#pragma unroll
        for (int m = 0; m < 8; ++m) {
            int n = i - 2 * m;
            if (n >= 0 && n < TAPS)
                fma2(A[m], W2[n <= RR ? n : 24 - n], P);
        }
    }

#pragma unroll
    for (int m = 0; m < 8; ++m) {
        float2 o = unpack2(A[m]);
        op[base + (2 * m)     * CC] = __float2half_rn(o.x);
        op[base + (2 * m + 1) * CC] = __float2half_rn(o.y);
    }
}

// ---------------- Pass 2: vertical, src folded into accumulator init --------
// Thread = one half2 column pair x 8 y outputs.  Issue order: 8 src LDG.64
// first (DRAM), then 32 tmp window loads (L2), then A[m] = -src, fma loop,
// stores.  Src latency overlaps window issue+latency instead of the tail.
__global__ void __launch_bounds__(256) pass_v_kernel(const float* __restrict__ src,
                                                     const float* __restrict__ k,
                                                     float* __restrict__ dst) {
    const int PAIRS = ROWF / 2;                     // 5376 pairs per row
    const int PER_B = (HH / 8) * PAIRS;             // 344,064 threads per batch
    int tid = blockIdx.x * 256 + threadIdx.x;

    int b   = tid / PER_B;
    int rem = tid - b * PER_B;
    int yg  = rem / PAIRS;
    int fp  = rem - yg * PAIRS;
    int y0  = yg * 8;

    size_t off = (size_t)b * IMGF + 2 * (size_t)fp;
    const __half* tp = g_tmp + off;
    const float*  sp = src + off;
    float*        dp = dst + off;

    u64 W2[13];
    load_weights(k, W2);

    // 1) src loads first: longest latency, overlapped by everything below.
    float2 s2[8];
#pragma unroll
    for (int m = 0; m < 8; ++m)
        s2[m] = *(const float2*)(sp + (size_t)(y0 + m) * ROWF);

    // 2) tmp window loads (L2-resident).
    __half2 v[32];
    if (y0 >= RR && y0 + 19 < HH) {
#pragma unroll
        for (int s = 0; s < 32; ++s)
            v[s] = *(const __half2*)(tp + (size_t)(y0 - RR + s) * ROWF);
    } else {
        const __half2 z = __float2half2_rn(0.0f);
#pragma unroll
        for (int s = 0; s < 32; ++s) {
            int yin = y0 - RR + s;
            v[s] = (yin >= 0 && yin < HH)
                       ? *(const __half2*)(tp + (size_t)yin * ROWF)
                       : z;
        }
    }

    // 3) accumulators start at -src (the src regs become the A regs).
    u64 A[8];
#pragma unroll
    for (int m = 0; m < 8; ++m)
        A[m] = pack2(-s2[m].x, -s2[m].y);

    // 4) fma loop.
#pragma unroll
    for (int s = 0; s < 32; ++s) {
        float2 f = __half22float2(v[s]);
        u64 P = pack2(f.x, f.y);
#pragma unroll
        for (int m = 0; m < 8; ++m) {
            int n = s - m;
            if (n >= 0 && n < TAPS)
                fma2(A[m], W2[n <= RR ? n : 24 - n], P);
        }
    }

    // 5) stores only.
#pragma unroll
    for (int m = 0; m < 8; ++m) {
        float2 o = unpack2(A[m]);
        *(float2*)(dp + (size_t)(y0 + m) * ROWF) = o;
    }
}

extern "C" void kernel_launch(void* const* d_in, const int* in_sizes, int n_in,
                              void* d_out, int out_size) {
    const float* src = (const float*)d_in[0];
    const float* k   = (const float*)d_in[1];
    float*       dst = (float*)d_out;

    int nthreads_h = BATCH * HH * (WW / 16) * CC;         // 1,376,256
    pass_h_kernel<<<nthreads_h / 256, 256>>>(src, k);

    int nthreads_v = BATCH * (HH / 8) * (ROWF / 2);       // 1,376,256
    pass_v_kernel<<<nthreads_v / 256, 256>>>(src, k, dst);
}